// round 1
// baseline (speedup 1.0000x reference)
#include <cuda_runtime.h>
#include <cuda_bf16.h>
#include <cstdint>
#include <cstdio>

// Problem constants
#define TT 1024
#define BB 128
#define HH 100
#define IN_ 100
#define GG 400   // 4*H
#define KC 100   // K-chunk for register-stationary GEMM

// ---------------- scratch (device globals: no allocs allowed) ----------------
__device__ float g_xT[(size_t)TT * BB * IN_];          // (T,B,IN)      52.4 MB
__device__ float g_gx[(size_t)2 * TT * BB * GG];       // (dir,T,B,4H) 419.4 MB
__device__ float g_mid[(size_t)TT * BB * 2 * HH];      // (T,B,2H)     104.9 MB

// ---------------- f32x2 helpers ----------------
__device__ __forceinline__ unsigned long long pk2(float a, float b) {
    unsigned long long r;
    asm("mov.b64 %0, {%1,%2};" : "=l"(r) : "f"(a), "f"(b));
    return r;
}
__device__ __forceinline__ unsigned long long fma2(unsigned long long a,
                                                   unsigned long long b,
                                                   unsigned long long c) {
    unsigned long long d;
    asm("fma.rn.f32x2 %0, %1, %2, %3;" : "=l"(d) : "l"(a), "l"(b), "l"(c));
    return d;
}
__device__ __forceinline__ float hsum2(unsigned long long a, unsigned long long b) {
    unsigned long long s;
    asm("add.rn.f32x2 %0, %1, %2;" : "=l"(s) : "l"(a), "l"(b));
    float lo, hi;
    asm("mov.b64 {%0,%1}, %2;" : "=f"(lo), "=f"(hi) : "l"(s));
    return lo + hi;
}

// ---------------- fast activations (MUFU-based, rel err ~1e-6) ----------------
__device__ __forceinline__ float fexp2(float x) {
    float r; asm("ex2.approx.f32 %0, %1;" : "=f"(r) : "f"(x)); return r;
}
__device__ __forceinline__ float frcpa(float x) {
    float r; asm("rcp.approx.f32 %0, %1;" : "=f"(r) : "f"(x)); return r;
}
__device__ __forceinline__ float fsig(float x) {
    // 1/(1+2^(-x*log2e))
    return frcpa(1.0f + fexp2(-1.4426950408889634f * x));
}
__device__ __forceinline__ float ftanh(float x) {
    // 2/(1+2^(-2x*log2e)) - 1
    return fmaf(2.0f, frcpa(1.0f + fexp2(-2.8853900817779268f * x)), -1.0f);
}

// ---------------- kernel 1: transpose x (B,IN,T) -> xT (T,B,IN) ----------------
__global__ void transpose_x(const float* __restrict__ x, float* __restrict__ xT) {
    __shared__ float tile[32][33];
    int b  = blockIdx.z;          // 0..127
    int k0 = blockIdx.y * 32;     // 0,32,64,96
    int t0 = blockIdx.x * 32;     // 0..992
    int tx = threadIdx.x, ty = threadIdx.y;   // 32 x 8
    #pragma unroll
    for (int i = ty; i < 32; i += 8) {
        int k = k0 + i;
        tile[i][tx] = (k < IN_) ? x[((size_t)b * IN_ + k) * TT + (t0 + tx)] : 0.0f;
    }
    __syncthreads();
    #pragma unroll
    for (int i = ty; i < 32; i += 8) {
        int t = t0 + i, k = k0 + tx;
        if (k < IN_)
            xT[((size_t)t * BB + b) * IN_ + k] = tile[tx][i];
    }
}

// ---------------- kernel 2: gx (+)= src(rows x K=100) @ W^T (+bias) ----------------
// Register-stationary W: thread j owns W[dir][j][kOff..kOff+99] as 50 f32x2 regs.
// Streams 16-row tiles of src through smem; rows broadcast to all 400 gate threads.
__global__ __launch_bounds__(416, 1) void gate_gemm(
    const float* __restrict__ src, int srcStride,     // row stride in floats
    const float* __restrict__ Wih, int wStride, int kOff,
    const float* __restrict__ bias,
    float* __restrict__ out, int accFlag)
{
    const int M = TT * BB;               // 131072 rows per direction
    const int CPD = 74;                  // CTAs per direction (grid = 148)
    const int RPC = 1776;                // rows per CTA (multiple of 16; 74*1776 >= M)
    int dir   = blockIdx.x / CPD;
    int chunk = blockIdx.x % CPD;
    int row0  = chunk * RPC;
    int rowHi = min(row0 + RPC, M);
    int j = threadIdx.x;

    __shared__ float stage[16][100];     // 6.4 KB row tile

    // load stationary weights + bias
    unsigned long long w[KC / 2];
    float bj = 0.0f;
    if (j < GG) {
        const float* wp = Wih + ((size_t)(dir * GG + j)) * wStride + kOff;
        #pragma unroll
        for (int q = 0; q < KC / 2; q++) {
            float2 tv = *(const float2*)(wp + 2 * q);
            w[q] = pk2(tv.x, tv.y);
        }
        bj = bias[dir * GG + j];
    }

    // tile prefetch mapping: thread j<400 -> (row r_ld, float4 q_ld)
    int r_ld = j / 25;
    int q_ld = (j % 25) * 4;
    float4 v = make_float4(0.f, 0.f, 0.f, 0.f);
    if (j < 400) {
        int rr = min(row0 + r_ld, M - 1);
        v = *(const float4*)(src + (size_t)rr * srcStride + q_ld);
    }

    int ntiles = (rowHi - row0 + 15) / 16;
    for (int tI = 0; tI < ntiles; tI++) {
        __syncthreads();                      // prior tile's readers done
        if (j < 400) *(float4*)&stage[r_ld][q_ld] = v;
        __syncthreads();                      // stage ready
        if (j < 400 && tI + 1 < ntiles) {     // prefetch next tile (overlaps compute)
            int rr = min(row0 + (tI + 1) * 16 + r_ld, M - 1);
            v = *(const float4*)(src + (size_t)rr * srcStride + q_ld);
        }
        if (j < GG) {
            int rlim = min(16, rowHi - row0 - tI * 16);
            for (int r = 0; r < rlim; r++) {
                unsigned long long a0 = 0, a1 = 0;
                #pragma unroll
                for (int q = 0; q < 25; q++) {
                    ulonglong2 hv = *(const ulonglong2*)&stage[r][4 * q];
                    a0 = fma2(w[2 * q],     hv.x, a0);
                    a1 = fma2(w[2 * q + 1], hv.y, a1);
                }
                float g = hsum2(a0, a1);
                size_t orow = (size_t)(row0 + tI * 16 + r);
                size_t oidx = ((size_t)dir * M + orow) * GG + j;
                out[oidx] = accFlag ? (out[oidx] + g) : (g + bj);
            }
        }
    }
}

// ---------------- kernel 3: the recurrence scan (one layer, both directions) ----
// grid = 128 CTAs: dir = blk>>6, batch pair = blk&63 (2 rows per CTA).
// Thread j<400 owns W_hh[dir][j][:] in 50 f32x2 regs; h broadcast from smem.
// Threads j<200 run the gate epilogue ((b,u) -> c,h update) and carry c in a reg.
__global__ __launch_bounds__(416, 1) void lstm_scan(
    const float* __restrict__ gx,     // (2,T,B,4H)
    const float* __restrict__ Whh,    // (2,4H,H)
    float* __restrict__ out)          // (T,B,2H)
{
    int dir  = blockIdx.x >> 6;
    int pair = blockIdx.x & 63;
    int b0r = pair * 2, b1r = b0r + 1;
    int j = threadIdx.x;

    __shared__ float sh_h[2][100];    // current h for both rows
    __shared__ float sg[2][400];      // gate exchange

    unsigned long long w[50];
    if (j < 400) {
        const float* wp = Whh + (size_t)(dir * GG + j) * HH;
        #pragma unroll
        for (int q = 0; q < 50; q++) {
            float2 tv = *(const float2*)(wp + 2 * q);
            w[q] = pk2(tv.x, tv.y);
        }
    }
    if (j < 100) { sh_h[0][j] = 0.0f; sh_h[1][j] = 0.0f; }

    float cst = 0.0f;                 // cell state (epilogue threads only)
    int bb = j / 100;                 // 0 or 1 for j<200
    int uu = j - bb * 100;

    int t = dir ? (TT - 1) : 0;
    size_t gxd = (size_t)dir * TT * BB * GG;
    float gA = 0.0f, gB = 0.0f;
    if (j < 400) {                    // prefetch first step's gx
        gA = gx[gxd + ((size_t)t * BB + b0r) * GG + j];
        gB = gx[gxd + ((size_t)t * BB + b1r) * GG + j];
    }
    __syncthreads();

    for (int it = 0; it < TT; it++) {
        if (j < 400) {
            unsigned long long a0 = 0, a1 = 0, a2 = 0, a3 = 0;
            #pragma unroll
            for (int q = 0; q < 25; q++) {
                ulonglong2 h0 = *(const ulonglong2*)&sh_h[0][4 * q];
                ulonglong2 h1 = *(const ulonglong2*)&sh_h[1][4 * q];
                a0 = fma2(w[2 * q],     h0.x, a0);
                a1 = fma2(w[2 * q + 1], h0.y, a1);
                a2 = fma2(w[2 * q],     h1.x, a2);
                a3 = fma2(w[2 * q + 1], h1.y, a3);
            }
            sg[0][j] = gA + hsum2(a0, a1);
            sg[1][j] = gB + hsum2(a2, a3);
            if (it + 1 < TT) {        // prefetch next step's gx (hidden by epilogue+GEMV)
                int tn = dir ? (t - 1) : (t + 1);
                gA = gx[gxd + ((size_t)tn * BB + b0r) * GG + j];
                gB = gx[gxd + ((size_t)tn * BB + b1r) * GG + j];
            }
        }
        __syncthreads();
        if (j < 200) {
            float gi = sg[bb][uu];
            float gf = sg[bb][100 + uu];
            float gg = sg[bb][200 + uu];
            float go = sg[bb][300 + uu];
            float iv = fsig(gi), fv = fsig(gf), gv = ftanh(gg), ov = fsig(go);
            cst = fv * cst + iv * gv;
            float h = ov * ftanh(cst);
            sh_h[bb][uu] = h;
            int brow = bb ? b1r : b0r;
            out[((size_t)t * BB + brow) * (2 * HH) + dir * HH + uu] = h;
        }
        __syncthreads();
        t = dir ? (t - 1) : (t + 1);
    }
}

// ---------------- launch ----------------
extern "C" void kernel_launch(void* const* d_in, const int* in_sizes, int n_in,
                              void* d_out, int out_size) {
    const float* x     = (const float*)d_in[0];
    const float* w_ih0 = (const float*)d_in[1];
    const float* w_hh0 = (const float*)d_in[2];
    const float* b0    = (const float*)d_in[3];
    const float* w_ih1 = (const float*)d_in[4];
    const float* w_hh1 = (const float*)d_in[5];
    const float* b1    = (const float*)d_in[6];
    float* out = (float*)d_out;

    float *pxT, *pgx, *pmid;
    cudaGetSymbolAddress((void**)&pxT,  g_xT);
    cudaGetSymbolAddress((void**)&pgx,  g_gx);
    cudaGetSymbolAddress((void**)&pmid, g_mid);

    // x -> xT (T,B,IN)
    transpose_x<<<dim3(TT / 32, 4, BB), dim3(32, 8)>>>(x, pxT);

    // layer 0: gx = xT @ w_ih0^T + b0 ; scan -> g_mid
    gate_gemm<<<148, 416>>>(pxT, IN_, w_ih0, IN_, 0, b0, pgx, 0);
    lstm_scan<<<128, 416>>>(pgx, w_hh0, pmid);

    // layer 1: gx = mid[:, :100] @ w_ih1[:, :, :100]^T + b1, then += mid[:,100:] @ w_ih1[:,:,100:]^T
    gate_gemm<<<148, 416>>>(pmid,       2 * HH, w_ih1, 2 * HH, 0,  b1, pgx, 0);
    gate_gemm<<<148, 416>>>(pmid + HH,  2 * HH, w_ih1, 2 * HH, HH, b1, pgx, 1);
    lstm_scan<<<128, 416>>>(pgx, w_hh1, out);
}